// round 1
// baseline (speedup 1.0000x reference)
#include <cuda_runtime.h>
#include <cuda_bf16.h>

typedef unsigned long long ull;

#define N_B    4
#define H_N    8
#define D_K    64
#define S_LEN  4096
#define L_LEN  4096
#define NH     (N_B * H_N)       // 32
#define ROWSTR (H_N * D_K)       // 512 floats between consecutive s/l rows
#define SPLIT  16
#define CHUNK  (S_LEN / SPLIT)   // 256
#define LT     64                // l-tile for output kernel

// Persistent scratch (device globals; no runtime allocation).
__device__ float g_partKV[SPLIT * NH * D_K * D_K];   // [split][nh][v][d]
__device__ float g_partKs[SPLIT * NH * D_K];         // [split][nh][d]
__device__ float g_KVt[NH * D_K * D_K];              // [nh][v][d]  (transposed KV)
__device__ float g_Ksum[NH * D_K];                   // [nh][d]

__device__ __forceinline__ float elu1(float x) {
    return x > 0.0f ? x + 1.0f : __expf(x);
}

// Packed dual-FMA: d = a*b + d on two fp32 lanes (Blackwell FFMA2 path).
__device__ __forceinline__ void fma2(ull& d, ull a, ull b) {
    asm("fma.rn.f32x2 %0, %1, %2, %0;" : "+l"(d) : "l"(a), "l"(b));
}
__device__ __forceinline__ float2 unpack2(ull p) {
    float2 r;
    asm("mov.b64 {%0, %1}, %2;" : "=f"(r.x), "=f"(r.y) : "l"(p));
    return r;
}

// ---------------------------------------------------------------------------
// Kernel 1: partial KV^T and partial Ksum over an S-chunk.
// Block = (split, nh). 256 threads; thread tile = 4 d x 4 v.
// smem K is stored DUPLICATED ([k,k] pairs) so the broadcast operand of the
// packed FMA comes straight out of an LDS.128 with zero pack MOVs.
// ---------------------------------------------------------------------------
__global__ void __launch_bounds__(256) kv_kernel(const float* __restrict__ Kg,
                                                 const float* __restrict__ Vg) {
    __shared__ float sKdup[8][128];       // 8 s-rows, each d duplicated
    __shared__ float sV[8][64];
    __shared__ float sStage[64 * 65];     // transpose staging, padded

    const int split = blockIdx.x;
    const int nh    = blockIdx.y;
    const int n     = nh >> 3;
    const int h     = nh & 7;

    const float* Kb = Kg + ((size_t)n * S_LEN + (size_t)split * CHUNK) * ROWSTR + h * D_K;
    const float* Vb = Vg + ((size_t)n * S_LEN + (size_t)split * CHUNK) * ROWSTR + h * D_K;

    const int t  = threadIdx.x;
    const int tv = t & 15;        // v tile index
    const int td = t >> 4;        // d tile index
    const int lrow = t >> 4;      // loader row 0..15
    const int lcol = (t & 15) * 4;

    ull acc[4][2];                // [d within tile][v-pair]
#pragma unroll
    for (int i = 0; i < 4; i++) { acc[i][0] = 0ull; acc[i][1] = 0ull; }
    float ksum = 0.0f;

    for (int sb = 0; sb < CHUNK; sb += 8) {
        const int srow = sb + (lrow & 7);
        if (lrow < 8) {
            float4 k4 = *(const float4*)(Kb + (size_t)srow * ROWSTR + lcol);
            k4.x = elu1(k4.x); k4.y = elu1(k4.y); k4.z = elu1(k4.z); k4.w = elu1(k4.w);
            float2* dst = (float2*)&sKdup[lrow][2 * lcol];
            dst[0] = make_float2(k4.x, k4.x);
            dst[1] = make_float2(k4.y, k4.y);
            dst[2] = make_float2(k4.z, k4.z);
            dst[3] = make_float2(k4.w, k4.w);
        } else {
            float4 v4 = *(const float4*)(Vb + (size_t)srow * ROWSTR + lcol);
            *(float4*)&sV[lrow - 8][lcol] = v4;
        }
        __syncthreads();

        if (t < 64) {   // warps 0-1 only: Ksum accumulation (d = t)
#pragma unroll
            for (int r = 0; r < 8; r++) ksum += sKdup[r][2 * t];
        }

#pragma unroll
        for (int r = 0; r < 8; r++) {
            ulonglong2 k01 = *(const ulonglong2*)&sKdup[r][8 * td];      // (k0,k0),(k1,k1)
            ulonglong2 k23 = *(const ulonglong2*)&sKdup[r][8 * td + 4];  // (k2,k2),(k3,k3)
            ulonglong2 vv  = *(const ulonglong2*)&sV[r][4 * tv];         // (v0,v1),(v2,v3)
            fma2(acc[0][0], k01.x, vv.x); fma2(acc[0][1], k01.x, vv.y);
            fma2(acc[1][0], k01.y, vv.x); fma2(acc[1][1], k01.y, vv.y);
            fma2(acc[2][0], k23.x, vv.x); fma2(acc[2][1], k23.x, vv.y);
            fma2(acc[3][0], k23.y, vv.x); fma2(acc[3][1], k23.y, vv.y);
        }
        __syncthreads();
    }

    // Stage transposed: sStage[v][d]
#pragma unroll
    for (int i = 0; i < 4; i++) {
#pragma unroll
        for (int j = 0; j < 2; j++) {
            float2 p = unpack2(acc[i][j]);
            const int d = 4 * td + i;
            const int v = 4 * tv + 2 * j;
            sStage[v * 65 + d]       = p.x;
            sStage[(v + 1) * 65 + d] = p.y;
        }
    }
    __syncthreads();

    float* dst = g_partKV + ((size_t)split * NH + nh) * (D_K * D_K);
    for (int idx = t; idx < D_K * D_K; idx += 256) {
        const int v = idx >> 6, d = idx & 63;
        dst[idx] = sStage[v * 65 + d];
    }
    if (t < 64) g_partKs[((size_t)split * NH + nh) * D_K + t] = ksum;
}

// ---------------------------------------------------------------------------
// Kernel 2: reduce partials across splits.
// ---------------------------------------------------------------------------
__global__ void __launch_bounds__(256) reduce_kernel() {
    const int nh  = blockIdx.x;
    const int idx = blockIdx.y * 256 + threadIdx.x;
    float s = 0.0f;
#pragma unroll
    for (int p = 0; p < SPLIT; p++)
        s += g_partKV[((size_t)p * NH + nh) * (D_K * D_K) + idx];
    g_KVt[(size_t)nh * (D_K * D_K) + idx] = s;

    if (blockIdx.y == 0 && threadIdx.x < 64) {
        float z = 0.0f;
#pragma unroll
        for (int p = 0; p < SPLIT; p++)
            z += g_partKs[((size_t)p * NH + nh) * D_K + threadIdx.x];
        g_Ksum[nh * D_K + threadIdx.x] = z;
    }
}

// ---------------------------------------------------------------------------
// Kernel 3: out[l][v] = (Qf[l] . KV[:,v]) / (Qf[l] . Ksum + eps)
// Pairs run along the REDUCTION dim d: Q rows give free d-pairs (row pad 68
// floats = 272B lane stride -> conflict-free LDS.128); KV^T rows are warp-
// broadcast (warp owns an 8-wide v group, lanes own l rows).
// ---------------------------------------------------------------------------
__global__ void __launch_bounds__(256) out_kernel(const float* __restrict__ Qg,
                                                  float* __restrict__ Og) {
    __shared__ float sQ[LT][68];          // feature-mapped Q tile, padded
    __shared__ float sKVt[D_K * D_K];     // [v][d]
    __shared__ float sKs[D_K];
    __shared__ float sZ[LT];

    const int nh = blockIdx.y;
    const int l0 = blockIdx.x * LT;
    const int n  = nh >> 3;
    const int h  = nh & 7;

    const float* Qb = Qg + ((size_t)n * L_LEN + l0) * ROWSTR + h * D_K;
    const int t = threadIdx.x;

    // Load + feature-map Q tile (64 rows x 64), coalesced float4.
    const int lrow = t >> 4;
    const int lcol = (t & 15) * 4;
#pragma unroll
    for (int rr = 0; rr < 4; rr++) {
        const int l = rr * 16 + lrow;
        float4 q = *(const float4*)(Qb + (size_t)l * ROWSTR + lcol);
        q.x = elu1(q.x); q.y = elu1(q.y); q.z = elu1(q.z); q.w = elu1(q.w);
        *(float4*)&sQ[l][lcol] = q;
    }
    // Load KV^T and Ksum.
    const float* kvsrc = g_KVt + (size_t)nh * (D_K * D_K);
    for (int idx = t; idx < D_K * D_K; idx += 256) sKVt[idx] = kvsrc[idx];
    if (t < 64) sKs[t] = g_Ksum[nh * D_K + t];
    __syncthreads();

    // Normalizer per row.
    if (t < LT) {
        float acc = 1e-6f;
#pragma unroll
        for (int d = 0; d < D_K; d++) acc += sQ[t][d] * sKs[d];
        sZ[t] = 1.0f / acc;
    }
    __syncthreads();

    const int w    = t >> 5;      // warp id -> v group
    const int lane = t & 31;      // -> l row (and l+32)
    const int vb   = w * 8;

    ull acc[2][8];
#pragma unroll
    for (int li = 0; li < 2; li++)
#pragma unroll
        for (int v = 0; v < 8; v++) acc[li][v] = 0ull;

    for (int d = 0; d < D_K; d += 4) {
        const ulonglong2 q0 = *(const ulonglong2*)&sQ[lane][d];
        const ulonglong2 q1 = *(const ulonglong2*)&sQ[lane + 32][d];
#pragma unroll
        for (int v = 0; v < 8; v++) {
            const ulonglong2 kv = *(const ulonglong2*)&sKVt[(vb + v) * D_K + d];
            fma2(acc[0][v], q0.x, kv.x); fma2(acc[0][v], q0.y, kv.y);
            fma2(acc[1][v], q1.x, kv.x); fma2(acc[1][v], q1.y, kv.y);
        }
    }

#pragma unroll
    for (int li = 0; li < 2; li++) {
        const int l = lane + 32 * li;
        const float z = sZ[l];
        float vals[8];
#pragma unroll
        for (int v = 0; v < 8; v++) {
            const float2 p = unpack2(acc[li][v]);
            vals[v] = (p.x + p.y) * z;
        }
        float* orow = Og + ((size_t)(n * L_LEN + l0 + l)) * ROWSTR + h * D_K + vb;
        *(float4*)(orow)     = make_float4(vals[0], vals[1], vals[2], vals[3]);
        *(float4*)(orow + 4) = make_float4(vals[4], vals[5], vals[6], vals[7]);
    }
}

// ---------------------------------------------------------------------------
extern "C" void kernel_launch(void* const* d_in, const int* in_sizes, int n_in,
                              void* d_out, int out_size) {
    (void)in_sizes; (void)n_in; (void)out_size;
    const float* Q = (const float*)d_in[0];
    const float* K = (const float*)d_in[1];
    const float* V = (const float*)d_in[2];
    float* O = (float*)d_out;

    kv_kernel<<<dim3(SPLIT, NH), 256>>>(K, V);
    reduce_kernel<<<dim3(NH, 16), 256>>>();
    out_kernel<<<dim3(L_LEN / LT, NH), 256>>>(Q, O);
}